// round 11
// baseline (speedup 1.0000x reference)
#include <cuda_runtime.h>
#include <cuda_bf16.h>

// out[b,p,h] = sum_{i,j} premise[b,p,i] * kernel[p,h,i,j] * hypothesis[b,h,j]
// B=8, P=96, H=96, D1=D2=128
//
// HBM-bound (604 MB K streamed once). One CTA per (p,h). Thread (w,l) owns
// columns 4l..4l+3 via LDG.128 read as ulonglong2 = two native f32x2 pairs.
// Premise staged DUPLICATED in smem ((v,v) per u64): mainloop per K row is
// 1 LDG.128 + 4 broadcast LDS.128 + 16 fma.rn.f32x2, zero packing.
//
// R11 change: 8 CTAs/SM (launch_bounds(128,8) -> 64-reg target) + unroll 4
// with immediate-consume premise loads to keep live registers ~52. 32 warps/SM
// of independent LDG streams to cover DRAM latency (R8/R10 both plateaued at
// ~75% DRAM at 24 warps regardless of instruction mix => latency-bound).

#define NB 8
#define NP 96
#define NH 96
#define ND 128

using u64 = unsigned long long;

__device__ __forceinline__ u64 fma2(u64 a, u64 b, u64 c) {
    u64 d;
    asm("fma.rn.f32x2 %0, %1, %2, %3;" : "=l"(d) : "l"(a), "l"(b), "l"(c));
    return d;
}
__device__ __forceinline__ u64 dup2(float v) {
    u64 r;
    asm("mov.b64 %0, {%1, %1};" : "=l"(r) : "f"(v));
    return r;
}
__device__ __forceinline__ void unpack2(u64 v, float& lo, float& hi) {
    asm("mov.b64 {%0, %1}, %2;" : "=f"(lo), "=f"(hi) : "l"(v));
}

__global__ void __launch_bounds__(128, 8)
interaction_kernel(const float* __restrict__ premise,
                   const float* __restrict__ hyp,
                   const float* __restrict__ kern,
                   float* __restrict__ out)
{
    const int h   = blockIdx.x;      // 0..95
    const int p   = blockIdx.y;      // 0..95
    const int tid = threadIdx.x;     // 0..127
    const int w   = tid >> 5;        // warp: rows i ≡ w (mod 4)
    const int l   = tid & 31;        // lane: columns 4l..4l+3

    __shared__ __align__(16) u64 pre_d[ND * NB];  // [i][b], (v,v) dup, 8 KB
    __shared__ float red[4][NB];

    // Stage premise[:, p, :] duplicated: pre_d[i*8 + b] = (v, v)
#pragma unroll
    for (int r = 0; r < 8; r++) {
        int idx = tid + r * 128;          // 0..1023
        int i = idx >> 3;
        int b = idx & 7;
        pre_d[idx] = dup2(premise[((size_t)b * NP + p) * ND + i]);
    }
    __syncthreads();

    // K tile: kernel[p,h,i,j]; this thread reads 16B at (i, 4l)
    const ulonglong2* kp = reinterpret_cast<const ulonglong2*>(
        kern + (((size_t)(p * NH + h)) << 14)) + l;   // row i -> kp[i*32]

    const ulonglong2* pre2 = reinterpret_cast<const ulonglong2*>(pre_d);

    // acc[b][jp]: f32x2 accumulator for columns (4l+2jp, 4l+2jp+1), batch b
    u64 acc[NB][2];
#pragma unroll
    for (int b = 0; b < NB; b++) { acc[b][0] = 0ull; acc[b][1] = 0ull; }

#pragma unroll 4
    for (int ii = 0; ii < 32; ii++) {
        const int i = w + 4 * ii;
        ulonglong2 kv = kp[i * 32];          // (k0,k1),(k2,k3) — native pairs
        // Consume each premise pair right after its LDS: only 2 u64 live.
#pragma unroll
        for (int bp = 0; bp < 4; bp++) {
            ulonglong2 pr = pre2[i * 4 + bp];   // dup pre[i][2bp], pre[i][2bp+1]
            acc[2 * bp + 0][0] = fma2(kv.x, pr.x, acc[2 * bp + 0][0]);
            acc[2 * bp + 0][1] = fma2(kv.y, pr.x, acc[2 * bp + 0][1]);
            acc[2 * bp + 1][0] = fma2(kv.x, pr.y, acc[2 * bp + 1][0]);
            acc[2 * bp + 1][1] = fma2(kv.y, pr.y, acc[2 * bp + 1][1]);
        }
    }

    // Epilogue: fold hypothesis[b, h, 4l..4l+3] (float4 = two f32x2 pairs)
    float s[NB];
#pragma unroll
    for (int b = 0; b < NB; b++) {
        ulonglong2 hv = *reinterpret_cast<const ulonglong2*>(
            &hyp[((size_t)b * NH + h) * ND + 4 * l]);
        u64 t = fma2(acc[b][0], hv.x, 0ull);
        t = fma2(acc[b][1], hv.y, t);
        float lo, hi;
        unpack2(t, lo, hi);
        s[b] = lo + hi;
    }

    // Reduce over 32 lanes (j dimension)
#pragma unroll
    for (int off = 16; off; off >>= 1) {
#pragma unroll
        for (int b = 0; b < NB; b++)
            s[b] += __shfl_down_sync(0xffffffffu, s[b], off);
    }

    if (l == 0) {
#pragma unroll
        for (int b = 0; b < NB; b++) red[w][b] = s[b];
    }
    __syncthreads();

    if (tid < NB) {
        float v = red[0][tid] + red[1][tid] + red[2][tid] + red[3][tid];
        out[((size_t)tid * NP + p) * NH + h] = v;
    }
}

extern "C" void kernel_launch(void* const* d_in, const int* in_sizes, int n_in,
                              void* d_out, int out_size) {
    const float* premise = (const float*)d_in[0];  // (8, 96, 128)
    const float* hyp     = (const float*)d_in[1];  // (8, 96, 128)
    const float* kern    = (const float*)d_in[2];  // (96, 96, 128, 128)
    float* out = (float*)d_out;                    // (8, 96, 96)

    dim3 grid(NH, NP);
    interaction_kernel<<<grid, 128>>>(premise, hyp, kern, out);
}

// round 12
// speedup vs baseline: 1.0068x; 1.0068x over previous
#include <cuda_runtime.h>
#include <cuda_bf16.h>
#include <cstdint>

// out[b,p,h] = sum_{i,j} premise[b,p,i] * kernel[p,h,i,j] * hypothesis[b,h,j]
// B=8, P=96, H=96, D1=D2=128
//
// HBM-bound (604 MB K streamed once). One CTA per (p,h). The 64 KB contiguous
// K tile is fetched with 8 x 8KB cp.async.bulk (TMA/UBLKCP) into smem, each
// chunk completing on its own mbarrier — in-flight DRAM bytes are decoupled
// from the register file (R8/R10/R11 showed register-batched LDG caps at
// ~75% DRAM). Warps consume chunks in order: warp w owns rows i = w (mod 4),
// lane l owns columns 4l..4l+3 (conflict-free LDS.128 = two native f32x2
// pairs). Premise staged duplicated ((v,v) u64) => zero-pack f32x2 mainloop.

#define NB 8
#define NP 96
#define NH 96
#define ND 128

#define STAGES     8
#define CHUNK_B    8192          // 16 rows * 512 B
#define CHUNK_ROWS 16

#define BAR_OFF 0                // 8 mbarriers * 8 B
#define PRE_OFF 128              // 8 KB dup premise
#define K_OFF   (PRE_OFF + 8192) // 64 KB K tile
#define SMEM_TOTAL (K_OFF + STAGES * CHUNK_B)

using u64 = unsigned long long;

__device__ __forceinline__ u64 fma2(u64 a, u64 b, u64 c) {
    u64 d;
    asm("fma.rn.f32x2 %0, %1, %2, %3;" : "=l"(d) : "l"(a), "l"(b), "l"(c));
    return d;
}
__device__ __forceinline__ u64 dup2(float v) {
    u64 r;
    asm("mov.b64 %0, {%1, %1};" : "=l"(r) : "f"(v));
    return r;
}
__device__ __forceinline__ void unpack2(u64 v, float& lo, float& hi) {
    asm("mov.b64 {%0, %1}, %2;" : "=f"(lo), "=f"(hi) : "l"(v));
}
__device__ __forceinline__ uint32_t smem_u32(const void* p) {
    uint32_t a;
    asm("{ .reg .u64 t; cvta.to.shared.u64 t, %1; cvt.u32.u64 %0, t; }"
        : "=r"(a) : "l"(p));
    return a;
}
__device__ __forceinline__ void mbar_wait(uint32_t mbar, uint32_t parity) {
    asm volatile(
        "{\n\t"
        ".reg .pred P1;\n\t"
        "WL_%=:\n\t"
        "mbarrier.try_wait.parity.acquire.cta.shared::cta.b64 P1, [%0], %1, 0x989680;\n\t"
        "@P1 bra.uni WD_%=;\n\t"
        "bra.uni WL_%=;\n\t"
        "WD_%=:\n\t"
        "}"
        :: "r"(mbar), "r"(parity) : "memory");
}

__global__ void __launch_bounds__(128)
interaction_kernel(const float* __restrict__ premise,
                   const float* __restrict__ hyp,
                   const float* __restrict__ kern,
                   float* __restrict__ out)
{
    extern __shared__ __align__(128) unsigned char smem_raw[];

    const int h   = blockIdx.x;      // 0..95
    const int p   = blockIdx.y;      // 0..95
    const int tid = threadIdx.x;     // 0..127
    const int w   = tid >> 5;        // warp: rows i ≡ w (mod 4)
    const int l   = tid & 31;        // lane: columns 4l..4l+3

    const uint32_t sbase = smem_u32(smem_raw);
    u64* pre_d = reinterpret_cast<u64*>(smem_raw + PRE_OFF);
    __shared__ float red[4][NB];

    // Init one mbarrier per chunk (arrive count 1 = the expect_tx arrival).
    if (tid == 0) {
#pragma unroll
        for (int c = 0; c < STAGES; c++)
            asm volatile("mbarrier.init.shared.b64 [%0], %1;"
                         :: "r"(sbase + BAR_OFF + 8 * c), "r"(1) : "memory");
    }
    __syncthreads();   // init visible to all waiters before any wait

    // Thread 0 issues ALL chunk copies immediately (64 KB contiguous tile).
    if (tid == 0) {
        const unsigned char* src = reinterpret_cast<const unsigned char*>(
            kern + (((size_t)(p * NH + h)) << 14));
#pragma unroll
        for (int c = 0; c < STAGES; c++) {
            const uint32_t bar = sbase + BAR_OFF + 8 * c;
            asm volatile("mbarrier.arrive.expect_tx.shared.b64 _, [%0], %1;"
                         :: "r"(bar), "r"(CHUNK_B) : "memory");
            asm volatile(
                "cp.async.bulk.shared::cluster.global.mbarrier::complete_tx::bytes "
                "[%0], [%1], %2, [%3];"
                :: "r"(sbase + K_OFF + c * CHUNK_B),
                   "l"(src + (size_t)c * CHUNK_B),
                   "r"(CHUNK_B), "r"(bar)
                : "memory");
        }
    }

    // Meanwhile: stage premise[:, p, :] duplicated: pre_d[i*8+b] = (v, v)
#pragma unroll
    for (int r = 0; r < 8; r++) {
        int idx = tid + r * 128;          // 0..1023
        int i = idx >> 3;
        int b = idx & 7;
        pre_d[idx] = dup2(premise[((size_t)b * NP + p) * ND + i]);
    }
    __syncthreads();   // premise ready for all warps

    const ulonglong2* pre2 = reinterpret_cast<const ulonglong2*>(pre_d);
    const ulonglong2* kbuf = reinterpret_cast<const ulonglong2*>(smem_raw + K_OFF);

    // acc[b][jp]: f32x2 accumulator for columns (4l+2jp, 4l+2jp+1), batch b
    u64 acc[NB][2];
#pragma unroll
    for (int b = 0; b < NB; b++) { acc[b][0] = 0ull; acc[b][1] = 0ull; }

    for (int c = 0; c < STAGES; c++) {
        mbar_wait(sbase + BAR_OFF + 8 * c, 0);
#pragma unroll
        for (int r = 0; r < CHUNK_ROWS / 4; r++) {
            const int i = c * CHUNK_ROWS + w + 4 * r;
            ulonglong2 kv = kbuf[i * 32 + l];    // LDS.128, conflict-free
            ulonglong2 pr01 = pre2[i * 4 + 0];   // broadcast LDS.128
            ulonglong2 pr23 = pre2[i * 4 + 1];
            ulonglong2 pr45 = pre2[i * 4 + 2];
            ulonglong2 pr67 = pre2[i * 4 + 3];
            u64 pr[NB] = { pr01.x, pr01.y, pr23.x, pr23.y,
                           pr45.x, pr45.y, pr67.x, pr67.y };
#pragma unroll
            for (int b = 0; b < NB; b++) {
                acc[b][0] = fma2(kv.x, pr[b], acc[b][0]);
                acc[b][1] = fma2(kv.y, pr[b], acc[b][1]);
            }
        }
    }

    // Epilogue: fold hypothesis[b, h, 4l..4l+3] (float4 = two f32x2 pairs)
    float s[NB];
#pragma unroll
    for (int b = 0; b < NB; b++) {
        ulonglong2 hv = *reinterpret_cast<const ulonglong2*>(
            &hyp[((size_t)b * NH + h) * ND + 4 * l]);
        u64 t = fma2(acc[b][0], hv.x, 0ull);
        t = fma2(acc[b][1], hv.y, t);
        float lo, hi;
        unpack2(t, lo, hi);
        s[b] = lo + hi;
    }

    // Reduce over 32 lanes (j dimension)
#pragma unroll
    for (int off = 16; off; off >>= 1) {
#pragma unroll
        for (int b = 0; b < NB; b++)
            s[b] += __shfl_down_sync(0xffffffffu, s[b], off);
    }

    if (l == 0) {
#pragma unroll
        for (int b = 0; b < NB; b++) red[w][b] = s[b];
    }
    __syncthreads();

    if (tid < NB) {
        float v = red[0][tid] + red[1][tid] + red[2][tid] + red[3][tid];
        out[((size_t)tid * NP + p) * NH + h] = v;
    }
}

extern "C" void kernel_launch(void* const* d_in, const int* in_sizes, int n_in,
                              void* d_out, int out_size) {
    const float* premise = (const float*)d_in[0];  // (8, 96, 128)
    const float* hyp     = (const float*)d_in[1];  // (8, 96, 128)
    const float* kern    = (const float*)d_in[2];  // (96, 96, 128, 128)
    float* out = (float*)d_out;                    // (8, 96, 96)

    cudaFuncSetAttribute(interaction_kernel,
                         cudaFuncAttributeMaxDynamicSharedMemorySize, SMEM_TOTAL);
    dim3 grid(NH, NP);
    interaction_kernel<<<grid, 128, SMEM_TOTAL>>>(premise, hyp, kern, out);
}

// round 13
// speedup vs baseline: 1.2098x; 1.2016x over previous
#include <cuda_runtime.h>
#include <cuda_bf16.h>
#include <cstdint>

// out[b,p,h] = sum_{i,j} premise[b,p,i] * kernel[p,h,i,j] * hypothesis[b,h,j]
// B=8, P=96, H=96, D1=D2=128
//
// HBM-bound (604 MB K streamed once). One CTA per (p,h). The 64 KB contiguous
// K tile is streamed through a 4-stage x 8 KB cp.async.bulk ring in smem:
// prologue issues chunks 0..3; after chunk c is consumed (+__syncthreads),
// tid0 re-issues chunk c+4 into stage c (parity flips on reuse). 40 KB smem
// -> 5 CTAs/SM (20 consumer warps, fixes R12's 8-warp consumption limit)
// while 5 x 32 KB = 160 KB/SM stays in flight off the register file.
// Mainloop per row per thread: 1 LDS.128 (K) + 4 broadcast LDS.128 (premise,
// staged duplicated (v,v)) + 16 fma.rn.f32x2, zero packing.

#define NB 8
#define NP 96
#define NH 96
#define ND 128

#define STAGES     4
#define NCHUNKS    8
#define CHUNK_B    8192          // 16 rows * 512 B
#define CHUNK_ROWS 16

#define BAR_OFF 0                // 4 mbarriers * 8 B
#define PRE_OFF 128              // 8 KB dup premise
#define K_OFF   (PRE_OFF + 8192) // 32 KB ring
#define SMEM_TOTAL (K_OFF + STAGES * CHUNK_B)   // 41088 B

using u64 = unsigned long long;

__device__ __forceinline__ u64 fma2(u64 a, u64 b, u64 c) {
    u64 d;
    asm("fma.rn.f32x2 %0, %1, %2, %3;" : "=l"(d) : "l"(a), "l"(b), "l"(c));
    return d;
}
__device__ __forceinline__ u64 dup2(float v) {
    u64 r;
    asm("mov.b64 %0, {%1, %1};" : "=l"(r) : "f"(v));
    return r;
}
__device__ __forceinline__ void unpack2(u64 v, float& lo, float& hi) {
    asm("mov.b64 {%0, %1}, %2;" : "=f"(lo), "=f"(hi) : "l"(v));
}
__device__ __forceinline__ uint32_t smem_u32(const void* p) {
    uint32_t a;
    asm("{ .reg .u64 t; cvta.to.shared.u64 t, %1; cvt.u32.u64 %0, t; }"
        : "=r"(a) : "l"(p));
    return a;
}
__device__ __forceinline__ void mbar_wait(uint32_t mbar, uint32_t parity) {
    asm volatile(
        "{\n\t"
        ".reg .pred P1;\n\t"
        "WL_%=:\n\t"
        "mbarrier.try_wait.parity.acquire.cta.shared::cta.b64 P1, [%0], %1, 0x989680;\n\t"
        "@P1 bra.uni WD_%=;\n\t"
        "bra.uni WL_%=;\n\t"
        "WD_%=:\n\t"
        "}"
        :: "r"(mbar), "r"(parity) : "memory");
}
__device__ __forceinline__ void issue_chunk(uint32_t bar, uint32_t dst,
                                            const unsigned char* src) {
    asm volatile("mbarrier.arrive.expect_tx.shared.b64 _, [%0], %1;"
                 :: "r"(bar), "r"(CHUNK_B) : "memory");
    asm volatile(
        "cp.async.bulk.shared::cluster.global.mbarrier::complete_tx::bytes "
        "[%0], [%1], %2, [%3];"
        :: "r"(dst), "l"(src), "r"(CHUNK_B), "r"(bar) : "memory");
}

__global__ void __launch_bounds__(128)
interaction_kernel(const float* __restrict__ premise,
                   const float* __restrict__ hyp,
                   const float* __restrict__ kern,
                   float* __restrict__ out)
{
    extern __shared__ __align__(128) unsigned char smem_raw[];

    const int h   = blockIdx.x;      // 0..95
    const int p   = blockIdx.y;      // 0..95
    const int tid = threadIdx.x;     // 0..127
    const int w   = tid >> 5;        // warp: rows ir ≡ w (mod 4) within chunk
    const int l   = tid & 31;        // lane: columns 4l..4l+3

    const uint32_t sbase = smem_u32(smem_raw);
    u64* pre_d = reinterpret_cast<u64*>(smem_raw + PRE_OFF);
    __shared__ float red[4][NB];

    const unsigned char* ksrc = reinterpret_cast<const unsigned char*>(
        kern + (((size_t)(p * NH + h)) << 14));

    // Init one mbarrier per stage (single expect_tx arrival per phase).
    if (tid == 0) {
#pragma unroll
        for (int s = 0; s < STAGES; s++)
            asm volatile("mbarrier.init.shared.b64 [%0], %1;"
                         :: "r"(sbase + BAR_OFF + 8 * s), "r"(1) : "memory");
    }
    __syncthreads();

    // Prologue: fill the ring (chunks 0..3 -> stages 0..3).
    if (tid == 0) {
#pragma unroll
        for (int s = 0; s < STAGES; s++)
            issue_chunk(sbase + BAR_OFF + 8 * s,
                        sbase + K_OFF + s * CHUNK_B,
                        ksrc + (size_t)s * CHUNK_B);
    }

    // Meanwhile: stage premise[:, p, :] duplicated: pre_d[i*8+b] = (v, v)
#pragma unroll
    for (int r = 0; r < 8; r++) {
        int idx = tid + r * 128;          // 0..1023
        int i = idx >> 3;
        int b = idx & 7;
        pre_d[idx] = dup2(premise[((size_t)b * NP + p) * ND + i]);
    }
    __syncthreads();

    const ulonglong2* pre2 = reinterpret_cast<const ulonglong2*>(pre_d);
    const ulonglong2* kbuf = reinterpret_cast<const ulonglong2*>(smem_raw + K_OFF);

    // acc[b][jp]: f32x2 accumulator for columns (4l+2jp, 4l+2jp+1), batch b
    u64 acc[NB][2];
#pragma unroll
    for (int b = 0; b < NB; b++) { acc[b][0] = 0ull; acc[b][1] = 0ull; }

#pragma unroll
    for (int c = 0; c < NCHUNKS; c++) {
        const int stage = c & (STAGES - 1);
        mbar_wait(sbase + BAR_OFF + 8 * stage, (c >= STAGES) ? 1u : 0u);

#pragma unroll
        for (int r = 0; r < CHUNK_ROWS / 4; r++) {
            const int ir = w + 4 * r;                 // row within chunk
            const int i  = c * CHUNK_ROWS + ir;       // row within tile
            ulonglong2 kv = kbuf[stage * 512 + ir * 32 + l];  // LDS.128
            ulonglong2 pr01 = pre2[i * 4 + 0];        // broadcast LDS.128
            ulonglong2 pr23 = pre2[i * 4 + 1];
            ulonglong2 pr45 = pre2[i * 4 + 2];
            ulonglong2 pr67 = pre2[i * 4 + 3];
            u64 pr[NB] = { pr01.x, pr01.y, pr23.x, pr23.y,
                           pr45.x, pr45.y, pr67.x, pr67.y };
#pragma unroll
            for (int b = 0; b < NB; b++) {
                acc[b][0] = fma2(kv.x, pr[b], acc[b][0]);
                acc[b][1] = fma2(kv.y, pr[b], acc[b][1]);
            }
        }

        // Recycle this stage for chunk c+4 (buffer-safe after the sync).
        if (c < NCHUNKS - STAGES) {
            __syncthreads();
            if (tid == 0)
                issue_chunk(sbase + BAR_OFF + 8 * stage,
                            sbase + K_OFF + stage * CHUNK_B,
                            ksrc + (size_t)(c + STAGES) * CHUNK_B);
        }
    }

    // Epilogue: fold hypothesis[b, h, 4l..4l+3] (float4 = two f32x2 pairs)
    float s[NB];
#pragma unroll
    for (int b = 0; b < NB; b++) {
        ulonglong2 hv = *reinterpret_cast<const ulonglong2*>(
            &hyp[((size_t)b * NH + h) * ND + 4 * l]);
        u64 t = fma2(acc[b][0], hv.x, 0ull);
        t = fma2(acc[b][1], hv.y, t);
        float lo, hi;
        unpack2(t, lo, hi);
        s[b] = lo + hi;
    }

    // Reduce over 32 lanes (j dimension)
#pragma unroll
    for (int off = 16; off; off >>= 1) {
#pragma unroll
        for (int b = 0; b < NB; b++)
            s[b] += __shfl_down_sync(0xffffffffu, s[b], off);
    }

    if (l == 0) {
#pragma unroll
        for (int b = 0; b < NB; b++) red[w][b] = s[b];
    }
    __syncthreads();

    if (tid < NB) {
        float v = red[0][tid] + red[1][tid] + red[2][tid] + red[3][tid];
        out[((size_t)tid * NP + p) * NH + h] = v;
    }
}

extern "C" void kernel_launch(void* const* d_in, const int* in_sizes, int n_in,
                              void* d_out, int out_size) {
    const float* premise = (const float*)d_in[0];  // (8, 96, 128)
    const float* hyp     = (const float*)d_in[1];  // (8, 96, 128)
    const float* kern    = (const float*)d_in[2];  // (96, 96, 128, 128)
    float* out = (float*)d_out;                    // (8, 96, 96)

    cudaFuncSetAttribute(interaction_kernel,
                         cudaFuncAttributeMaxDynamicSharedMemorySize, SMEM_TOTAL);
    dim3 grid(NH, NP);
    interaction_kernel<<<grid, 128, SMEM_TOTAL>>>(premise, hyp, kern, out);
}